// round 6
// baseline (speedup 1.0000x reference)
#include <cuda_runtime.h>
#include <math_constants.h>

// Problem constants (from reference): x [4,4096,2048] f32, W [64,2048] f32, b [64] f32
// Output: concat( normalized_weights [16384,2] f32 , top2_indices [16384,2] as f32 )

#define D_MODEL   2048
#define NEXPERT   64
#define TOPK      2
#define BT        32      // tokens per CTA
#define KC        32      // K-chunk
#define NTHREADS  128

__global__ __launch_bounds__(NTHREADS)
void router_topk_kernel(const float* __restrict__ x,
                        const float* __restrict__ W,
                        const float* __restrict__ b,
                        float* __restrict__ out,
                        int n_tokens,
                        int out_elems)
{
    __shared__ float xs[BT][KC + 1];        // +1 pad: conflict-free column reads
    __shared__ float ws[NEXPERT][KC + 1];
    __shared__ float ls[BT][NEXPERT + 1];   // logits for epilogue

    const int tid = threadIdx.x;
    const int tg  = tid >> 4;     // 0..7  -> token group (4 tokens each)
    const int eg  = tid & 15;     // 0..15 -> expert group (4 experts each)
    const int t0  = tg * 4;
    const int e0  = eg * 4;
    const int tok_base = blockIdx.x * BT;

    // Accumulators initialized with bias (same bias for every token row)
    float acc[4][4];
    {
        float bj0 = b[e0 + 0], bj1 = b[e0 + 1], bj2 = b[e0 + 2], bj3 = b[e0 + 3];
        #pragma unroll
        for (int i = 0; i < 4; i++) {
            acc[i][0] = bj0; acc[i][1] = bj1; acc[i][2] = bj2; acc[i][3] = bj3;
        }
    }

    for (int kb = 0; kb < D_MODEL; kb += KC) {
        // ---- load x tile: 32 tokens x 32 k = 1024 floats (2 float4 / thread) ----
        #pragma unroll
        for (int i = 0; i < 2; i++) {
            int lin = i * 512 + tid * 4;          // 0..1023
            int t   = lin >> 5;                   // 0..31
            int kk  = lin & 31;                   // multiple of 4
            float4 v = *reinterpret_cast<const float4*>(
                &x[(size_t)(tok_base + t) * D_MODEL + kb + kk]);
            xs[t][kk + 0] = v.x; xs[t][kk + 1] = v.y;
            xs[t][kk + 2] = v.z; xs[t][kk + 3] = v.w;
        }
        // ---- load W tile: 64 experts x 32 k = 2048 floats (4 float4 / thread) ----
        #pragma unroll
        for (int i = 0; i < 4; i++) {
            int lin = i * 512 + tid * 4;          // 0..2047
            int e   = lin >> 5;                   // 0..63
            int kk  = lin & 31;
            float4 v = *reinterpret_cast<const float4*>(
                &W[(size_t)e * D_MODEL + kb + kk]);
            ws[e][kk + 0] = v.x; ws[e][kk + 1] = v.y;
            ws[e][kk + 2] = v.z; ws[e][kk + 3] = v.w;
        }
        __syncthreads();

        // ---- compute: 4x4 microtile, 16 FMA per k-step ----
        #pragma unroll
        for (int k = 0; k < KC; k++) {
            float xr[4], wr[4];
            #pragma unroll
            for (int i = 0; i < 4; i++) xr[i] = xs[t0 + i][k];
            #pragma unroll
            for (int j = 0; j < 4; j++) wr[j] = ws[e0 + j][k];
            #pragma unroll
            for (int i = 0; i < 4; i++)
                #pragma unroll
                for (int j = 0; j < 4; j++)
                    acc[i][j] = fmaf(xr[i], wr[j], acc[i][j]);
        }
        __syncthreads();
    }

    // ---- stash logits to smem ----
    #pragma unroll
    for (int i = 0; i < 4; i++)
        #pragma unroll
        for (int j = 0; j < 4; j++)
            ls[t0 + i][e0 + j] = acc[i][j];
    __syncthreads();

    // ---- epilogue: one thread per token, top-2 + renormalized softmax ----
    if (tid < BT) {
        const int t = tid;
        float m1 = -CUDART_INF_F, m2 = -CUDART_INF_F;
        int   i1 = 0, i2 = 0;
        #pragma unroll 8
        for (int e = 0; e < NEXPERT; e++) {
            float v = ls[t][e];
            if (v > m1)      { m2 = m1; i2 = i1; m1 = v; i1 = e; }
            else if (v > m2) { m2 = v;  i2 = e; }
        }
        // normalized top-2 softmax: exp(l1)/(exp(l1)+exp(l2)), exp(l2)/(...)
        float w2    = expf(m2 - m1);
        float inv   = 1.0f / (1.0f + w2);
        int   gt    = tok_base + t;

        out[(size_t)gt * 2 + 0] = inv;
        out[(size_t)gt * 2 + 1] = w2 * inv;

        // indices block follows all weights (tuple outputs concatenated)
        size_t idx_off = (size_t)n_tokens * 2;
        if ((size_t)out_elems >= idx_off + (size_t)n_tokens * 2) {
            out[idx_off + (size_t)gt * 2 + 0] = (float)i1;
            out[idx_off + (size_t)gt * 2 + 1] = (float)i2;
        }
    }
}

extern "C" void kernel_launch(void* const* d_in, const int* in_sizes, int n_in,
                              void* d_out, int out_size)
{
    const float* x = (const float*)d_in[0];   // [B*S, 2048]
    const float* W = (const float*)d_in[1];   // [64, 2048]
    const float* b = (const float*)d_in[2];   // [64]
    float* out = (float*)d_out;

    int n_tokens = in_sizes[0] / D_MODEL;     // 16384
    int n_blocks = n_tokens / BT;             // 512

    router_topk_kernel<<<n_blocks, NTHREADS>>>(x, W, b, out, n_tokens, out_size);
}

// round 7
// speedup vs baseline: 1.0016x; 1.0016x over previous
#include <cuda_runtime.h>
#include <math_constants.h>

// x [16384, 2048] f32, W [64, 2048] f32, b [64] f32
// out = concat( normalized_top2_weights [16384,2] f32 , top2_indices [16384,2] as f32 )

#define D_MODEL   2048
#define NEXPERT   64
#define BT        32      // tokens per CTA
#define KC        32      // K-chunk
#define NTHREADS  128
#define XPAD      36      // row pad (floats): 16B-aligned rows, 2-way max bank conflict

// packed dual-FMA: {d.lo,d.hi} += {a.lo,a.hi} * {b.lo,b.hi}
__device__ __forceinline__ void fma2(unsigned long long& d,
                                     unsigned long long a,
                                     unsigned long long b) {
    asm("fma.rn.f32x2 %0, %1, %2, %0;" : "+l"(d) : "l"(a), "l"(b));
}

__global__ __launch_bounds__(NTHREADS)
void router_topk_kernel(const float* __restrict__ x,
                        const float* __restrict__ W,
                        const float* __restrict__ b,
                        float* __restrict__ out,
                        int n_tokens,
                        int out_elems)
{
    __shared__ __align__(16) float xs[BT][XPAD];
    __shared__ __align__(16) float ws[NEXPERT][XPAD];
    __shared__ float ls[BT][NEXPERT + 1];

    const int tid = threadIdx.x;
    const int tg  = tid >> 4;              // 0..7  -> token group (4 tokens)
    const int eg  = tid & 15;              // 0..15 -> expert lanes; e = eg + 16*j
    const int t0  = tg * 4;
    const int tok_base = blockIdx.x * BT;

    // f32x2 accumulators: even-k / odd-k partial sums packed per (token, expert)
    unsigned long long acc[4][4];
    #pragma unroll
    for (int i = 0; i < 4; i++)
        #pragma unroll
        for (int j = 0; j < 4; j++)
            acc[i][j] = 0ull;

    for (int kb = 0; kb < D_MODEL; kb += KC) {
        // ---- x tile: 32 tok x 32 k = 1024 floats -> 2 float4 / thread ----
        #pragma unroll
        for (int it = 0; it < 2; it++) {
            int lin = it * 512 + tid * 4;
            int t   = lin >> 5;
            int kk  = lin & 31;
            float4 v = *reinterpret_cast<const float4*>(
                &x[(size_t)(tok_base + t) * D_MODEL + kb + kk]);
            *reinterpret_cast<float4*>(&xs[t][kk]) = v;
        }
        // ---- W tile: 64 exp x 32 k = 2048 floats -> 4 float4 / thread ----
        #pragma unroll
        for (int it = 0; it < 4; it++) {
            int lin = it * 512 + tid * 4;
            int e   = lin >> 5;
            int kk  = lin & 31;
            float4 v = *reinterpret_cast<const float4*>(
                &W[(size_t)e * D_MODEL + kb + kk]);
            *reinterpret_cast<float4*>(&ws[e][kk]) = v;
        }
        __syncthreads();

        // ---- compute: per 4-k step, 8x LDS.128 + 32x FFMA2 (64 MACs) ----
        #pragma unroll
        for (int kk = 0; kk < KC; kk += 4) {
            unsigned long long xv[4][2], wv[4][2];
            #pragma unroll
            for (int i = 0; i < 4; i++) {
                ulonglong2 v = *reinterpret_cast<const ulonglong2*>(&xs[t0 + i][kk]);
                xv[i][0] = v.x; xv[i][1] = v.y;
            }
            #pragma unroll
            for (int j = 0; j < 4; j++) {
                ulonglong2 v = *reinterpret_cast<const ulonglong2*>(&ws[eg + 16 * j][kk]);
                wv[j][0] = v.x; wv[j][1] = v.y;
            }
            #pragma unroll
            for (int i = 0; i < 4; i++)
                #pragma unroll
                for (int j = 0; j < 4; j++) {
                    fma2(acc[i][j], xv[i][0], wv[j][0]);
                    fma2(acc[i][j], xv[i][1], wv[j][1]);
                }
        }
        __syncthreads();
    }

    // ---- combine k-parity halves + bias, stash logits ----
    #pragma unroll
    for (int i = 0; i < 4; i++)
        #pragma unroll
        for (int j = 0; j < 4; j++) {
            float2 f = *reinterpret_cast<float2*>(&acc[i][j]);
            int e = eg + 16 * j;
            ls[t0 + i][e] = f.x + f.y + __ldg(&b[e]);
        }
    __syncthreads();

    // ---- epilogue: one thread per token, top-2 + renormalized softmax ----
    if (tid < BT) {
        const int t = tid;
        float m1 = -CUDART_INF_F, m2 = -CUDART_INF_F;
        int   i1 = 0, i2 = 0;
        #pragma unroll 8
        for (int e = 0; e < NEXPERT; e++) {
            float v = ls[t][e];
            if (v > m1)      { m2 = m1; i2 = i1; m1 = v; i1 = e; }
            else if (v > m2) { m2 = v;  i2 = e; }
        }
        float w2  = expf(m2 - m1);
        float inv = 1.0f / (1.0f + w2);
        int   gt  = tok_base + t;

        out[(size_t)gt * 2 + 0] = inv;
        out[(size_t)gt * 2 + 1] = w2 * inv;

        size_t idx_off = (size_t)n_tokens * 2;
        if ((size_t)out_elems >= idx_off + (size_t)n_tokens * 2) {
            out[idx_off + (size_t)gt * 2 + 0] = (float)i1;
            out[idx_off + (size_t)gt * 2 + 1] = (float)i2;
        }
    }
}

extern "C" void kernel_launch(void* const* d_in, const int* in_sizes, int n_in,
                              void* d_out, int out_size)
{
    const float* x = (const float*)d_in[0];
    const float* W = (const float*)d_in[1];
    const float* b = (const float*)d_in[2];
    float* out = (float*)d_out;

    int n_tokens = in_sizes[0] / D_MODEL;     // 16384
    int n_blocks = n_tokens / BT;             // 512

    router_topk_kernel<<<n_blocks, NTHREADS>>>(x, W, b, out, n_tokens, out_size);
}

// round 9
// speedup vs baseline: 1.0603x; 1.0586x over previous
#include <cuda_runtime.h>
#include <math_constants.h>

// x [16384, 2048] f32, W [64, 2048] f32, b [64] f32
// out = concat( normalized_top2_weights [16384,2] f32 , top2_indices [16384,2] as f32 )

#define D_MODEL   2048
#define NEXPERT   64
#define BT        64              // tokens per CTA
#define KC        32              // k per chunk
#define KP        (KC / 2)        // 16 packed-k rows
#define NTHREADS  128
#define NCHUNK    (D_MODEL / KC)  // 64

typedef unsigned long long ull;

// packed dual-FMA: {d.lo,d.hi} += {a.lo,a.hi} * {b.lo,b.hi}
__device__ __forceinline__ void fma2(ull& d, ull a, ull b) {
    asm("fma.rn.f32x2 %0, %1, %2, %0;" : "+l"(d) : "l"(a), "l"(b));
}
__device__ __forceinline__ ull pack2(float lo, float hi) {
    ull r; asm("mov.b64 %0, {%1, %2};" : "=l"(r) : "f"(lo), "f"(hi)); return r;
}

__global__ __launch_bounds__(NTHREADS)
void router_topk_kernel(const float* __restrict__ x,
                        const float* __restrict__ W,
                        const float* __restrict__ bias,
                        float* __restrict__ out,
                        int n_tokens, int out_elems)
{
    // x tile, transposed & k-pair packed: xsP[kp][t] = {x[t][2kp], x[t][2kp+1]}
    __shared__ ull  xsP[KP][BT + 1];          // 16 x 65 ull  (pad -> conflict-free STS)
    __shared__ ull  ws2[NEXPERT][KP];         // 64 x 16 ull  (128B rows, broadcast reads)
    __shared__ float ls[BT][NEXPERT + 1];     // logits for epilogue

    const int tid  = threadIdx.x;
    const int lane = tid & 31;
    const int wrp  = tid >> 5;                // 0..3
    const int e0   = wrp * 16;                // this warp's expert block
    const int tok_base = blockIdx.x * BT;

    const int tq = tid >> 3;                  // 0..15 (row helper for loads)
    const int ts = tid & 7;                   // 0..7  (k-group helper)
    const int kk0 = 4 * ts;                   // k offset of this thread's float4
    const int kp0 = 2 * ts;                   // packed-k row

    // f32x2 accumulators: acc0 = token 'lane', acc1 = token 'lane+32'
    ull acc0[16], acc1[16];
    #pragma unroll
    for (int j = 0; j < 16; j++) { acc0[j] = 0ull; acc1[j] = 0ull; }

    // register-staged global loads (prefetch next chunk during compute)
    float4 px[4], pw[4];

    auto ldg_chunk = [&](int c, float4* lx, float4* lw) {
        const int kb = c * KC;
        #pragma unroll
        for (int i = 0; i < 4; i++) {
            int r = 16 * i + tq;              // token row (0..63) / expert row (0..63)
            lx[i] = *reinterpret_cast<const float4*>(
                &x[(size_t)(tok_base + r) * D_MODEL + kb + kk0]);
            lw[i] = *reinterpret_cast<const float4*>(
                &W[(size_t)r * D_MODEL + kb + kk0]);
        }
    };

    ldg_chunk(0, px, pw);

    for (int c = 0; c < NCHUNK; c++) {
        // ---- stage registers -> smem (transpose+pack x, pack W) ----
        #pragma unroll
        for (int i = 0; i < 4; i++) {
            int r = 16 * i + tq;
            xsP[kp0    ][r] = pack2(px[i].x, px[i].y);
            xsP[kp0 + 1][r] = pack2(px[i].z, px[i].w);
            ulonglong2 wv;
            wv.x = pack2(pw[i].x, pw[i].y);
            wv.y = pack2(pw[i].z, pw[i].w);
            *reinterpret_cast<ulonglong2*>(&ws2[r][kp0]) = wv;
        }
        __syncthreads();

        // ---- prefetch next chunk (latency hidden by compute below) ----
        int cn = (c + 1 < NCHUNK) ? (c + 1) : c;
        ldg_chunk(cn, px, pw);

        // ---- compute: per 4-k step: 4 LDS.64 + 16 bcast LDS.128 + 64 FFMA2 ----
        #pragma unroll 4
        for (int m = 0; m < KP; m += 2) {
            ull xa00 = xsP[m    ][lane];
            ull xa01 = xsP[m + 1][lane];
            ull xa10 = xsP[m    ][lane + 32];
            ull xa11 = xsP[m + 1][lane + 32];
            #pragma unroll
            for (int j = 0; j < 16; j++) {
                ulonglong2 w = *reinterpret_cast<const ulonglong2*>(&ws2[e0 + j][m]);
                fma2(acc0[j], xa00, w.x);
                fma2(acc0[j], xa01, w.y);
                fma2(acc1[j], xa10, w.x);
                fma2(acc1[j], xa11, w.y);
            }
        }
        __syncthreads();
    }

    // ---- combine k-parity halves + bias, stash logits ----
    #pragma unroll
    for (int j = 0; j < 16; j++) {
        int e = e0 + j;
        float be = __ldg(&bias[e]);
        float2 f0 = *reinterpret_cast<float2*>(&acc0[j]);
        float2 f1 = *reinterpret_cast<float2*>(&acc1[j]);
        ls[lane     ][e] = f0.x + f0.y + be;
        ls[lane + 32][e] = f1.x + f1.y + be;
    }
    __syncthreads();

    // ---- epilogue: one thread per token, top-2 + renormalized softmax ----
    if (tid < BT) {
        const int t = tid;
        float m1 = -CUDART_INF_F, m2 = -CUDART_INF_F;
        int   i1 = 0, i2 = 0;
        #pragma unroll 8
        for (int e = 0; e < NEXPERT; e++) {
            float v = ls[t][e];
            if (v > m1)      { m2 = m1; i2 = i1; m1 = v; i1 = e; }
            else if (v > m2) { m2 = v;  i2 = e; }
        }
        float w2  = expf(m2 - m1);
        float inv = 1.0f / (1.0f + w2);
        int   gt  = tok_base + t;

        out[(size_t)gt * 2 + 0] = inv;
        out[(size_t)gt * 2 + 1] = w2 * inv;

        size_t idx_off = (size_t)n_tokens * 2;
        if ((size_t)out_elems >= idx_off + (size_t)n_tokens * 2) {
            out[idx_off + (size_t)gt * 2 + 0] = (float)i1;
            out[idx_off + (size_t)gt * 2 + 1] = (float)i2;
        }
    }
}

extern "C" void kernel_launch(void* const* d_in, const int* in_sizes, int n_in,
                              void* d_out, int out_size)
{
    const float* x = (const float*)d_in[0];
    const float* W = (const float*)d_in[1];
    const float* b = (const float*)d_in[2];
    float* out = (float*)d_out;

    int n_tokens = in_sizes[0] / D_MODEL;     // 16384
    int n_blocks = n_tokens / BT;             // 256

    router_topk_kernel<<<n_blocks, NTHREADS>>>(x, W, b, out, n_tokens, out_size);
}